// round 11
// baseline (speedup 1.0000x reference)
#include <cuda_runtime.h>
#include <math.h>
#include <stdint.h>

// ---------------------------------------------------------------------------
// Problem constants
//   L=2 layers, H=1024, XD=192, YD=64, IN=256, B=256, PRE_LEN=64, FWD_LEN=48
// ---------------------------------------------------------------------------
#define LB   256          // batch
#define LH   1024         // hidden
#define XD   192
#define YD   64
#define PRE_LEN 64
#define FWD_LEN 48

// ---------------------------------------------------------------------------
// Device-global scratch (no cudaMalloc allowed)
// ---------------------------------------------------------------------------
__device__ float g_W0[4096 * 1280];   // packed [w_ih_0 | w_hh_0], gate-interleaved rows
__device__ float g_W1[4096 * 2048];   // packed [w_ih_1 | w_hh_1], gate-interleaved rows
__device__ float g_b0[4096];          // b_ih_0 + b_hh_0, gate-interleaved
__device__ float g_b1[4096];
__device__ float g_h0buf[2][LB * LH];
__device__ float g_h1buf[2][LB * LH];
__device__ float g_c0[LB * LH];
__device__ float g_c1[LB * LH];
__device__ float g_tmp[LB * LH];      // fc1 output
__device__ float g_est[LB * YD];      // running est / last_y

// ---------------------------------------------------------------------------
// Helpers
// ---------------------------------------------------------------------------
__device__ __forceinline__ unsigned long long brd(float x) {
    unsigned long long r;
    asm("mov.b64 %0, {%1, %1};" : "=l"(r) : "f"(x));
    return r;
}
__device__ __forceinline__ unsigned long long ffma2(unsigned long long a,
                                                    unsigned long long b,
                                                    unsigned long long c) {
    unsigned long long d;
    asm("fma.rn.f32x2 %0, %1, %2, %3;" : "=l"(d) : "l"(a), "l"(b), "l"(c));
    return d;
}
__device__ __forceinline__ float2 unpk(unsigned long long v) {
    float2 f;
    asm("mov.b64 {%0, %1}, %2;" : "=f"(f.x), "=f"(f.y) : "l"(v));
    return f;
}
// accurate tanh via expm1 (no cancellation, no overflow)
__device__ __forceinline__ float tanh_acc(float x) {
    float ax = fabsf(x);
    float t  = expm1f(-2.0f * ax);
    float r  = -t / (t + 2.0f);
    return x < 0.0f ? -r : r;
}
__device__ __forceinline__ float sig_acc(float x) {
    if (x >= 0.0f) return 1.0f / (1.0f + expf(-x));
    float e = expf(x);
    return e / (1.0f + e);
}

// ---------------------------------------------------------------------------
// Weight packing: packed row r = j*4 + gate  (gate order i,f,g,o; j = 0..1023)
// columns: [w_ih (IN) | w_hh (H)]
// ---------------------------------------------------------------------------
__global__ void pack0_kernel(const float* __restrict__ wih, const float* __restrict__ whh,
                             const float* __restrict__ bih, const float* __restrict__ bhh) {
    const int total = 4096 * 1280;
    for (int idx = blockIdx.x * blockDim.x + threadIdx.x; idx < total;
         idx += gridDim.x * blockDim.x) {
        int r = idx / 1280, k = idx - r * 1280;
        int j = r >> 2, g = r & 3;
        int n = g * 1024 + j;
        g_W0[idx] = (k < 256) ? wih[n * 256 + k] : whh[n * 1024 + (k - 256)];
        if (idx < 4096) {
            int jj = idx >> 2, gg = idx & 3;
            int nn = gg * 1024 + jj;
            g_b0[idx] = bih[nn] + bhh[nn];
        }
    }
}
__global__ void pack1_kernel(const float* __restrict__ wih, const float* __restrict__ whh,
                             const float* __restrict__ bih, const float* __restrict__ bhh) {
    const int total = 4096 * 2048;
    for (int idx = blockIdx.x * blockDim.x + threadIdx.x; idx < total;
         idx += gridDim.x * blockDim.x) {
        int r = idx / 2048, k = idx - r * 2048;
        int j = r >> 2, g = r & 3;
        int n = g * 1024 + j;
        g_W1[idx] = (k < 1024) ? wih[n * 1024 + k] : whh[n * 1024 + (k - 1024)];
        if (idx < 4096) {
            int jj = idx >> 2, gg = idx & 3;
            int nn = gg * 1024 + jj;
            g_b1[idx] = bih[nn] + bhh[nn];
        }
    }
}

__global__ void init_kernel(const float* __restrict__ pre_y) {
    const int stride = gridDim.x * blockDim.x;
    const int i0 = blockIdx.x * blockDim.x + threadIdx.x;
    for (int idx = i0; idx < LB * LH; idx += stride) {
        g_h0buf[0][idx] = 0.0f;
        g_h1buf[0][idx] = 0.0f;
        g_c0[idx] = 0.0f;
        g_c1[idx] = 0.0f;
    }
    for (int idx = i0; idx < LB * YD; idx += stride)
        g_est[idx] = pre_y[(PRE_LEN - 1) * LB * YD + idx];
}

// ---------------------------------------------------------------------------
// Fused GEMM (+bias) + epilogue.
//   C[m, r] = sum_k A[m, k] * W[r, k] + bias[r]
//   A assembled from up to 3 row-major segments: (s0,w0) ++ (s1,w1) ++ (s2,1024)
//   CTA tile 64(M) x 128(N), 128 threads, 8x8 microtile, FFMA2 pairs over N.
//   EPI==0: LSTM cell (packed gates, writes hout & cio), N = 4096, grid.y = 32
//   EPI==1: tanh     (writes hout = tanh(z+b)),          N = 1024, grid.y = 8
// ---------------------------------------------------------------------------
template <int KTOT, int EPI>
__global__ void __launch_bounds__(128)
gemm_step(const float* __restrict__ W, const float* __restrict__ bias,
          const float* __restrict__ s0, int w0,
          const float* __restrict__ s1, int w1,
          const float* __restrict__ s2,
          float* __restrict__ hout, float* __restrict__ cio) {
    constexpr int NC = KTOT / 16;
    __shared__ float As[2][16 * 68];    // k-major, padded stride 68
    __shared__ float Ws[2][16 * 132];   // k-major, padded stride 132

    const int tid  = threadIdx.x;
    const int bm   = blockIdx.x;        // 0..3   (M/64)
    const int bn   = blockIdx.y;        // N/128
    const int mIdx = tid >> 4;          // 0..7
    const int nIdx = tid & 15;          // 0..15

    float4 ra[2], rw[4];
    unsigned long long acc[8][4];
#pragma unroll
    for (int i = 0; i < 8; i++)
#pragma unroll
        for (int p = 0; p < 4; p++) acc[i][p] = 0ull;

    auto ldg_chunk = [&](int c) {
        const int k0 = c * 16;
#pragma unroll
        for (int i = 0; i < 2; i++) {
            int f4 = tid + 128 * i;
            int ml = f4 >> 2;
            int k  = k0 + (f4 & 3) * 4;
            int m  = bm * 64 + ml;
            const float* p;
            if (k < w0)           p = s0 + (size_t)m * w0 + k;
            else if (k < w0 + w1) p = s1 + (size_t)m * w1 + (k - w0);
            else                  p = s2 + (size_t)m * 1024 + (k - w0 - w1);
            ra[i] = *(const float4*)p;
        }
#pragma unroll
        for (int i = 0; i < 4; i++) {
            int f4 = tid + 128 * i;
            int r  = f4 >> 2;
            int k  = k0 + (f4 & 3) * 4;
            rw[i]  = *(const float4*)(W + (size_t)(bn * 128 + r) * KTOT + k);
        }
    };
    auto sts_chunk = [&](int b) {
#pragma unroll
        for (int i = 0; i < 2; i++) {
            int f4 = tid + 128 * i;
            int ml = f4 >> 2;
            int kc = (f4 & 3) * 4;
            float* q = &As[b][0];
            q[(kc + 0) * 68 + ml] = ra[i].x;
            q[(kc + 1) * 68 + ml] = ra[i].y;
            q[(kc + 2) * 68 + ml] = ra[i].z;
            q[(kc + 3) * 68 + ml] = ra[i].w;
        }
#pragma unroll
        for (int i = 0; i < 4; i++) {
            int f4 = tid + 128 * i;
            int r  = f4 >> 2;
            int kc = (f4 & 3) * 4;
            float* q = &Ws[b][0];
            q[(kc + 0) * 132 + r] = rw[i].x;
            q[(kc + 1) * 132 + r] = rw[i].y;
            q[(kc + 2) * 132 + r] = rw[i].z;
            q[(kc + 3) * 132 + r] = rw[i].w;
        }
    };
    auto compute_chunk = [&](int b) {
#pragma unroll
        for (int kk = 0; kk < 16; kk++) {
            const float* ap = &As[b][kk * 68 + mIdx * 8];
            float4 a0 = *(const float4*)(ap);
            float4 a1 = *(const float4*)(ap + 4);
            unsigned long long av[8];
            av[0] = brd(a0.x); av[1] = brd(a0.y); av[2] = brd(a0.z); av[3] = brd(a0.w);
            av[4] = brd(a1.x); av[5] = brd(a1.y); av[6] = brd(a1.z); av[7] = brd(a1.w);
            const ulonglong2* wp = (const ulonglong2*)&Ws[b][kk * 132 + nIdx * 8];
            ulonglong2 wA = wp[0], wB = wp[1];
            unsigned long long wv0 = wA.x, wv1 = wA.y, wv2 = wB.x, wv3 = wB.y;
#pragma unroll
            for (int mi = 0; mi < 8; mi++) {
                acc[mi][0] = ffma2(av[mi], wv0, acc[mi][0]);
                acc[mi][1] = ffma2(av[mi], wv1, acc[mi][1]);
                acc[mi][2] = ffma2(av[mi], wv2, acc[mi][2]);
                acc[mi][3] = ffma2(av[mi], wv3, acc[mi][3]);
            }
        }
    };

    ldg_chunk(0);
    sts_chunk(0);
    __syncthreads();
#pragma unroll 1
    for (int c = 0; c < NC; c++) {
        if (c + 1 < NC) ldg_chunk(c + 1);
        compute_chunk(c & 1);
        if (c + 1 < NC) {
            sts_chunk((c + 1) & 1);
            __syncthreads();
        }
    }

    // ---- epilogue ----
    const int r0 = bn * 128 + nIdx * 8;   // aligned to 8 -> two whole gate quads
#pragma unroll
    for (int mi = 0; mi < 8; mi++) {
        const int m = bm * 64 + mIdx * 8 + mi;
        float z[8];
#pragma unroll
        for (int p = 0; p < 4; p++) {
            float2 f = unpk(acc[mi][p]);
            z[2 * p] = f.x;
            z[2 * p + 1] = f.y;
        }
        if (EPI == 1) {
#pragma unroll
            for (int rr = 0; rr < 8; rr++)
                hout[(size_t)m * 1024 + r0 + rr] = tanh_acc(z[rr] + bias[r0 + rr]);
        } else {
#pragma unroll
            for (int q = 0; q < 2; q++) {
                float zi = z[4 * q + 0] + bias[r0 + 4 * q + 0];
                float zf = z[4 * q + 1] + bias[r0 + 4 * q + 1];
                float zg = z[4 * q + 2] + bias[r0 + 4 * q + 2];
                float zo = z[4 * q + 3] + bias[r0 + 4 * q + 3];
                int j   = (r0 >> 2) + q;
                int idx = m * 1024 + j;
                float cold = cio[idx];
                float cn = sig_acc(zf) * cold + sig_acc(zi) * tanh_acc(zg);
                cio[idx]  = cn;
                hout[idx] = sig_acc(zo) * tanh_acc(cn);
            }
        }
    }
}

// ---------------------------------------------------------------------------
// fc2: est_new = tmp @ fc_w2.T + fc_b2 + est_old ; write est & out[t]
// One warp per batch row m; lanes split K=1024; coalesced w2 reads.
// ---------------------------------------------------------------------------
__global__ void fc2_kernel(const float* __restrict__ tmp, const float* __restrict__ w2,
                           const float* __restrict__ b2, float* __restrict__ est,
                           float* __restrict__ outp) {
    const int warp = threadIdx.x >> 5;
    const int lane = threadIdx.x & 31;
    const int m = blockIdx.x * 8 + warp;    // grid 32 * 8 warps = 256
    float a[32];
#pragma unroll
    for (int i = 0; i < 32; i++) a[i] = tmp[(size_t)m * 1024 + lane + 32 * i];
#pragma unroll 1
    for (int n = 0; n < 64; n++) {
        const float* wr = w2 + (size_t)n * 1024 + lane;
        float s = 0.0f;
#pragma unroll
        for (int i = 0; i < 32; i++) s = fmaf(a[i], wr[32 * i], s);
#pragma unroll
        for (int off = 16; off; off >>= 1) s += __shfl_xor_sync(0xffffffffu, s, off);
        if (lane == 0) {
            float v = s + b2[n] + est[m * 64 + n];
            est[m * 64 + n]  = v;
            outp[m * 64 + n] = v;
        }
    }
}

// ---------------------------------------------------------------------------
// Host driver (graph-capturable: kernel launches only)
// ---------------------------------------------------------------------------
extern "C" void kernel_launch(void* const* d_in, const int* in_sizes, int n_in,
                              void* d_out, int out_size) {
    const float* pre_x  = (const float*)d_in[0];
    const float* pre_y  = (const float*)d_in[1];
    const float* fwd_x  = (const float*)d_in[2];
    const float* w_ih_0 = (const float*)d_in[3];
    const float* w_hh_0 = (const float*)d_in[4];
    const float* b_ih_0 = (const float*)d_in[5];
    const float* b_hh_0 = (const float*)d_in[6];
    const float* w_ih_1 = (const float*)d_in[7];
    const float* w_hh_1 = (const float*)d_in[8];
    const float* b_ih_1 = (const float*)d_in[9];
    const float* b_hh_1 = (const float*)d_in[10];
    const float* fc_w1  = (const float*)d_in[11];
    const float* fc_b1  = (const float*)d_in[12];
    const float* fc_w2  = (const float*)d_in[13];
    const float* fc_b2  = (const float*)d_in[14];
    float* out = (float*)d_out;

    float *W0, *W1, *b0, *b1, *h0base, *h1base, *c0, *c1, *tmp, *est;
    cudaGetSymbolAddress((void**)&W0, g_W0);
    cudaGetSymbolAddress((void**)&W1, g_W1);
    cudaGetSymbolAddress((void**)&b0, g_b0);
    cudaGetSymbolAddress((void**)&b1, g_b1);
    cudaGetSymbolAddress((void**)&h0base, g_h0buf);
    cudaGetSymbolAddress((void**)&h1base, g_h1buf);
    cudaGetSymbolAddress((void**)&c0, g_c0);
    cudaGetSymbolAddress((void**)&c1, g_c1);
    cudaGetSymbolAddress((void**)&tmp, g_tmp);
    cudaGetSymbolAddress((void**)&est, g_est);

    float* h0[2] = {h0base, h0base + LB * LH};
    float* h1[2] = {h1base, h1base + LB * LH};

    pack0_kernel<<<1024, 256>>>(w_ih_0, w_hh_0, b_ih_0, b_hh_0);
    pack1_kernel<<<1024, 256>>>(w_ih_1, w_hh_1, b_ih_1, b_hh_1);
    init_kernel<<<512, 256>>>(pre_y);

    dim3 gl(4, 32);   // LSTM GEMMs: N = 4096
    dim3 gf(4, 8);    // fc1:        N = 1024
    int p0 = 0, p1 = 0;

    // -------- warmup encode over concat(pre_x, pre_y) --------
    for (int t = 0; t < PRE_LEN; t++) {
        gemm_step<1280, 0><<<gl, 128>>>(W0, b0,
            pre_x + (size_t)t * LB * XD, XD,
            pre_y + (size_t)t * LB * YD, YD,
            h0[p0], h0[p0 ^ 1], c0);
        gemm_step<2048, 0><<<gl, 128>>>(W1, b1,
            h0[p0 ^ 1], 1024, h1[p1], 1024, h0[p0],
            h1[p1 ^ 1], c1);
        p0 ^= 1; p1 ^= 1;
    }

    // -------- autoregressive decode --------
    for (int t = 0; t < FWD_LEN; t++) {
        gemm_step<1024, 1><<<gf, 128>>>(fc_w1, fc_b1,
            h1[p1], 1024, h1[p1], 0, h1[p1],
            tmp, c0 /*unused*/);
        fc2_kernel<<<32, 256>>>(tmp, fc_w2, fc_b2, est, out + (size_t)t * LB * YD);
        gemm_step<1280, 0><<<gl, 128>>>(W0, b0,
            fwd_x + (size_t)t * LB * XD, XD,
            est, YD,
            h0[p0], h0[p0 ^ 1], c0);
        gemm_step<2048, 0><<<gl, 128>>>(W1, b1,
            h0[p0 ^ 1], 1024, h1[p1], 1024, h0[p0],
            h1[p1 ^ 1], c1);
        p0 ^= 1; p1 ^= 1;
    }
}